// round 2
// baseline (speedup 1.0000x reference)
#include <cuda_runtime.h>
#include <cuda_bf16.h>
#include <cstdint>

// Problem constants (fixed by the dataset)
#define B_DIM   16
#define N_DIM   50000
#define E_DIM   1600000
#define CLAMP_MIN_F (-10.0f)
#define CLAMP_MAX_F ( 10.0f)
#define EPS_F   (1e-6f)

// Transposed (N, B) scratch: each node's 16 batch values are contiguous (64B).
// 3 x 3.2MB = 9.6MB -> fully L2-resident.
__device__ float g_ET [N_DIM * B_DIM];   // E transposed
__device__ float g_OT [N_DIM * B_DIM];   // o_pre transposed
__device__ float g_ACC[N_DIM * B_DIM];   // accumulator, init to E + chem_influence

// ---------------------------------------------------------------------------
// Kernel A: transpose + init accumulator, node-major.
// One thread per node n. For each fixed b, consecutive threads read
// consecutive n -> fully coalesced LDG. Writes are 3 x 64B contiguous
// blocks per thread -> fully coalesced STG.128 (no strided sectors).
// ---------------------------------------------------------------------------
__global__ void prep_kernel(const float* __restrict__ chem,
                            const float* __restrict__ E,
                            const float* __restrict__ o_pre)
{
    int n = blockIdx.x * blockDim.x + threadIdx.x;
    if (n >= N_DIM) return;

    float et[B_DIM], ot[B_DIM], ac[B_DIM];
    #pragma unroll
    for (int b = 0; b < B_DIM; b++) {
        float e = __ldg(&E    [b * N_DIM + n]);
        float o = __ldg(&o_pre[b * N_DIM + n]);
        float c = __ldg(&chem [b * N_DIM + n]);
        et[b] = e;
        ot[b] = o;
        ac[b] = e + c;     // fold chem_influence into the accumulator init
    }

    float4* pe = reinterpret_cast<float4*>(&g_ET [n * B_DIM]);
    float4* po = reinterpret_cast<float4*>(&g_OT [n * B_DIM]);
    float4* pa = reinterpret_cast<float4*>(&g_ACC[n * B_DIM]);
    #pragma unroll
    for (int q = 0; q < 4; q++) {
        pe[q] = make_float4(et[q*4], et[q*4+1], et[q*4+2], et[q*4+3]);
        po[q] = make_float4(ot[q*4], ot[q*4+1], ot[q*4+2], ot[q*4+3]);
        pa[q] = make_float4(ac[q*4], ac[q*4+1], ac[q*4+2], ac[q*4+3]);
    }
}

// ---------------------------------------------------------------------------
// Kernel B: edge scatter, one thread per edge.
// 3 coalesced scalar LDG (src/dst/w) + 8 LDG.128 gathers (each edge's 16
// batch values are contiguous 64B in OT/ET) + 4 RED.128 (no-return L2-side
// adds). 15 memory instructions per edge vs 24 in the lane-split version.
// ---------------------------------------------------------------------------
__global__ void edge_kernel(const float* __restrict__ w,
                            const int*   __restrict__ src,
                            const int*   __restrict__ dst)
{
    int e = blockIdx.x * blockDim.x + threadIdx.x;
    if (e >= E_DIM) return;

    int   s  = __ldg(&src[e]);
    int   d  = __ldg(&dst[e]);
    float wv = __ldg(&w[e]);

    const float4* po = reinterpret_cast<const float4*>(&g_OT[s * B_DIM]);
    const float4* pt = reinterpret_cast<const float4*>(&g_ET[d * B_DIM]);

    #pragma unroll
    for (int q = 0; q < 4; q++) {
        float4 Oj = po[q];
        float4 En = pt[q];
        float4 c;
        c.x = (Oj.x >= En.x) ? (Oj.x * wv) : (-Oj.x * wv);
        c.y = (Oj.y >= En.y) ? (Oj.y * wv) : (-Oj.y * wv);
        c.z = (Oj.z >= En.z) ? (Oj.z * wv) : (-Oj.z * wv);
        c.w = (Oj.w >= En.w) ? (Oj.w * wv) : (-Oj.w * wv);

        float* p = &g_ACC[d * B_DIM + q * 4];
        asm volatile("red.global.add.v4.f32 [%0], {%1, %2, %3, %4};"
                     :: "l"(p), "f"(c.x), "f"(c.y), "f"(c.z), "f"(c.w)
                     : "memory");
    }
}

// ---------------------------------------------------------------------------
// Kernel C: epilogue. tid = b*N + n so threshold/decay/E reads and the two
// output writes are coalesced; the g_ACC read is 64B-strided (L2 hit, cheap).
// ---------------------------------------------------------------------------
__global__ void final_kernel(const float* __restrict__ E,
                             const float* __restrict__ threshold,
                             const float* __restrict__ decay,
                             float* __restrict__ out)
{
    int tid = blockIdx.x * blockDim.x + threadIdx.x;
    if (tid >= B_DIM * N_DIM) return;
    int b = tid / N_DIM;
    int n = tid - b * N_DIM;

    float S = g_ACC[n * B_DIM + b];
    S = fminf(fmaxf(S, CLAMP_MIN_F), CLAMP_MAX_F);

    float thr = threshold[n];
    float dec = decay[n];
    float Ev  = E[tid];

    bool  gt    = S > thr;
    float new_o = fmaxf(S - thr, 0.0f);
    bool  mask  = (!gt) && (fabsf(S - Ev) <= EPS_F);
    float new_e = gt ? new_o : (mask ? (Ev - dec) : S);

    out[tid]                 = new_o;
    out[B_DIM * N_DIM + tid] = new_e;
}

// ---------------------------------------------------------------------------
// Launch. Inputs (metadata order):
//   0 chem_influence (B,N) f32   1 E (B,N) f32       2 o_pre (B,N) f32
//   3 w (E,) f32                 4 threshold (N,) f32 5 decay (N,) f32
//   6 src (E,) i32               7 dst (E,) i32
// Output: new_o (B,N) then new_e (B,N) concatenated, f32.
// ---------------------------------------------------------------------------
extern "C" void kernel_launch(void* const* d_in, const int* in_sizes, int n_in,
                              void* d_out, int out_size)
{
    const float* chem  = (const float*)d_in[0];
    const float* E     = (const float*)d_in[1];
    const float* o_pre = (const float*)d_in[2];
    const float* w     = (const float*)d_in[3];
    const float* thr   = (const float*)d_in[4];
    const float* dec   = (const float*)d_in[5];
    const int*   src   = (const int*)  d_in[6];
    const int*   dst   = (const int*)  d_in[7];
    float* out = (float*)d_out;

    const int THREADS = 256;
    int node_blocks = (N_DIM + THREADS - 1) / THREADS;
    int bn_blocks   = (B_DIM * N_DIM + THREADS - 1) / THREADS;
    int edge_blocks = (E_DIM + THREADS - 1) / THREADS;

    prep_kernel <<<node_blocks, THREADS>>>(chem, E, o_pre);
    edge_kernel <<<edge_blocks, THREADS>>>(w, src, dst);
    final_kernel<<<bn_blocks,   THREADS>>>(E, thr, dec, out);
}

// round 3
// speedup vs baseline: 1.9382x; 1.9382x over previous
#include <cuda_runtime.h>
#include <cuda_bf16.h>
#include <cstdint>

// Problem constants (fixed by the dataset)
#define B_DIM   16
#define N_DIM   50000
#define E_DIM   1600000
#define CLAMP_MIN_F (-10.0f)
#define CLAMP_MAX_F ( 10.0f)
#define EPS_F   (1e-6f)

// Transposed (N, B) scratch: each node's 16 batch values are contiguous (64B).
// 3 x 3.2MB = 9.6MB -> fully L2-resident.
__device__ float g_ET [N_DIM * B_DIM];   // E transposed
__device__ float g_OT [N_DIM * B_DIM];   // o_pre transposed
__device__ float g_ACC[N_DIM * B_DIM];   // accumulator, init to E + chem_influence

// ---------------------------------------------------------------------------
// Kernel A: transpose + init accumulator, q-split node-major.
// tid = q*N + n : thread handles batches b = 4q..4q+3 of node n.
// For fixed (q,b), consecutive threads read consecutive n -> coalesced LDG.
// Each thread writes one float4 per array at n*16 + q*4: 64B stride between
// threads, but every sector of every touched line is written -> full lines.
// 200k threads (4x R2's parallelism) to cover latency.
// ---------------------------------------------------------------------------
__global__ void prep_kernel(const float* __restrict__ chem,
                            const float* __restrict__ E,
                            const float* __restrict__ o_pre)
{
    int tid = blockIdx.x * blockDim.x + threadIdx.x;
    if (tid >= 4 * N_DIM) return;
    int q = tid / N_DIM;          // 0..3 (batch quad)
    int n = tid - q * N_DIM;      // node

    float et[4], ot[4], ac[4];
    #pragma unroll
    for (int j = 0; j < 4; j++) {
        int b = q * 4 + j;
        float e = __ldg(&E    [b * N_DIM + n]);
        float o = __ldg(&o_pre[b * N_DIM + n]);
        float c = __ldg(&chem [b * N_DIM + n]);
        et[j] = e;
        ot[j] = o;
        ac[j] = e + c;            // fold chem_influence into accumulator init
    }

    int t = n * B_DIM + q * 4;
    *reinterpret_cast<float4*>(&g_ET [t]) = make_float4(et[0], et[1], et[2], et[3]);
    *reinterpret_cast<float4*>(&g_OT [t]) = make_float4(ot[0], ot[1], ot[2], ot[3]);
    *reinterpret_cast<float4*>(&g_ACC[t]) = make_float4(ac[0], ac[1], ac[2], ac[3]);
}

// ---------------------------------------------------------------------------
// Kernel B: edge scatter. 4 lanes per edge; each lane owns one batch quad
// (float4). The quad's 4 lanes load contiguous 16B pieces of the edge's 64B
// block -> one 64B request per quad (8 wavefronts per warp instruction, not
// 32). __ldg routes the gathers through L1 (avg degree 32 -> real reuse).
// red.global.add.v4.f32 -> no-return L2-side add, one RED.128 per lane.
// ---------------------------------------------------------------------------
__global__ void edge_kernel(const float* __restrict__ w,
                            const int*   __restrict__ src,
                            const int*   __restrict__ dst)
{
    int t = blockIdx.x * blockDim.x + threadIdx.x;
    if (t >= E_DIM * 4) return;
    int e = t >> 2;
    int q = t & 3;

    int   s  = __ldg(&src[e]);
    int   d  = __ldg(&dst[e]);
    float wv = __ldg(&w[e]);

    const float4 Oj = __ldg(reinterpret_cast<const float4*>(&g_OT[s * B_DIM + q * 4]));
    const float4 En = __ldg(reinterpret_cast<const float4*>(&g_ET[d * B_DIM + q * 4]));

    float4 c;
    c.x = (Oj.x >= En.x) ? (Oj.x * wv) : (-Oj.x * wv);
    c.y = (Oj.y >= En.y) ? (Oj.y * wv) : (-Oj.y * wv);
    c.z = (Oj.z >= En.z) ? (Oj.z * wv) : (-Oj.z * wv);
    c.w = (Oj.w >= En.w) ? (Oj.w * wv) : (-Oj.w * wv);

    float* p = &g_ACC[d * B_DIM + q * 4];
    asm volatile("red.global.add.v4.f32 [%0], {%1, %2, %3, %4};"
                 :: "l"(p), "f"(c.x), "f"(c.y), "f"(c.z), "f"(c.w)
                 : "memory");
}

// ---------------------------------------------------------------------------
// Kernel C: epilogue, q-split node-major (tid = q*N + n).
// ACC read is one contiguous LDG.128 per thread (L2 hit); threshold/decay/E
// and both output stores are coalesced for every fixed b.
// ---------------------------------------------------------------------------
__global__ void final_kernel(const float* __restrict__ E,
                             const float* __restrict__ threshold,
                             const float* __restrict__ decay,
                             float* __restrict__ out)
{
    int tid = blockIdx.x * blockDim.x + threadIdx.x;
    if (tid >= 4 * N_DIM) return;
    int q = tid / N_DIM;
    int n = tid - q * N_DIM;

    float4 Sv  = *reinterpret_cast<const float4*>(&g_ACC[n * B_DIM + q * 4]);
    float  thr = __ldg(&threshold[n]);
    float  dec = __ldg(&decay[n]);

    float Sa[4] = {Sv.x, Sv.y, Sv.z, Sv.w};
    #pragma unroll
    for (int j = 0; j < 4; j++) {
        int b = q * 4 + j;
        float S  = fminf(fmaxf(Sa[j], CLAMP_MIN_F), CLAMP_MAX_F);
        float Ev = __ldg(&E[b * N_DIM + n]);

        bool  gt    = S > thr;
        float new_o = fmaxf(S - thr, 0.0f);
        bool  mask  = (!gt) && (fabsf(S - Ev) <= EPS_F);
        float new_e = gt ? new_o : (mask ? (Ev - dec) : S);

        out[b * N_DIM + n]                 = new_o;
        out[B_DIM * N_DIM + b * N_DIM + n] = new_e;
    }
}

// ---------------------------------------------------------------------------
// Launch. Inputs (metadata order):
//   0 chem_influence (B,N) f32   1 E (B,N) f32       2 o_pre (B,N) f32
//   3 w (E,) f32                 4 threshold (N,) f32 5 decay (N,) f32
//   6 src (E,) i32               7 dst (E,) i32
// Output: new_o (B,N) then new_e (B,N) concatenated, f32.
// ---------------------------------------------------------------------------
extern "C" void kernel_launch(void* const* d_in, const int* in_sizes, int n_in,
                              void* d_out, int out_size)
{
    const float* chem  = (const float*)d_in[0];
    const float* E     = (const float*)d_in[1];
    const float* o_pre = (const float*)d_in[2];
    const float* w     = (const float*)d_in[3];
    const float* thr   = (const float*)d_in[4];
    const float* dec   = (const float*)d_in[5];
    const int*   src   = (const int*)  d_in[6];
    const int*   dst   = (const int*)  d_in[7];
    float* out = (float*)d_out;

    const int THREADS = 256;
    int qn_blocks   = (4 * N_DIM + THREADS - 1) / THREADS;
    int edge_blocks = (E_DIM * 4 + THREADS - 1) / THREADS;

    prep_kernel <<<qn_blocks,   THREADS>>>(chem, E, o_pre);
    edge_kernel <<<edge_blocks, THREADS>>>(w, src, dst);
    final_kernel<<<qn_blocks,   THREADS>>>(E, thr, dec, out);
}